// round 12
// baseline (speedup 1.0000x reference)
#include <cuda_runtime.h>
#include <cuda_bf16.h>
#include <cuda_fp16.h>
#include <math.h>
#include <stdint.h>

#define B_SZ 256
#define T_SZ 256
#define D_RAW 409
#define D_PAD 416
#define H_SZ 1024
#define G4 4096
#define CELL_SZ 512
#define MROWS (B_SZ * T_SZ)
#define XLD 40
#define RN_NBLK 128          // persistent recurrence grid (1 CTA/SM)
#define LO_SCALE 2048.0f
#define LO_INV   (1.0f / 2048.0f)

typedef __nv_bfloat16 bf16;

// ---------------- static device scratch ------------------------------------
__device__ bf16   g_xcat_hi[(size_t)MROWS * D_PAD];
__device__ bf16   g_xcat_lo[(size_t)MROWS * D_PAD];
__device__ bf16   g_Wih_hi[G4 * D_PAD];
__device__ bf16   g_Wih_lo[G4 * D_PAD];
__device__ __half g_Whh_h[G4 * H_SZ];       // rows permuted: r = 4*j + gate
__device__ __half g_Whh_l[G4 * H_SZ];       // (W - hi) * 2048
__device__ float  g_xg[(size_t)T_SZ * B_SZ * G4];   // [t][b][n_perm]
__device__ __half g_hf[2][B_SZ * H_SZ];     // h (fp16), double-buffered
__device__ float  g_h[B_SZ * H_SZ];         // fp32 h at t=255 (for MLP)
__device__ float  g_hidden[B_SZ * CELL_SZ];
__device__ unsigned g_bar_arrive;
__device__ unsigned g_bar_gen;

// ---------------- helpers --------------------------------------------------
__device__ __forceinline__ uint32_t smem_u32(const void* p) {
    return (uint32_t)__cvta_generic_to_shared(p);
}
__device__ __forceinline__ void ldsm4(uint32_t& r0, uint32_t& r1, uint32_t& r2,
                                      uint32_t& r3, uint32_t a) {
    asm volatile("ldmatrix.sync.aligned.m8n8.x4.shared.b16 {%0,%1,%2,%3}, [%4];"
                 : "=r"(r0), "=r"(r1), "=r"(r2), "=r"(r3) : "r"(a));
}
__device__ __forceinline__ void mma16816_bf(float c[4], const uint32_t a[4],
                                            uint32_t b0, uint32_t b1) {
    asm volatile(
        "mma.sync.aligned.m16n8k16.row.col.f32.bf16.bf16.f32 "
        "{%0,%1,%2,%3}, {%4,%5,%6,%7}, {%8,%9}, {%0,%1,%2,%3};"
        : "+f"(c[0]), "+f"(c[1]), "+f"(c[2]), "+f"(c[3])
        : "r"(a[0]), "r"(a[1]), "r"(a[2]), "r"(a[3]), "r"(b0), "r"(b1));
}
__device__ __forceinline__ void mma16816_f16(float c[4], const uint32_t a[4],
                                             uint32_t b0, uint32_t b1) {
    asm volatile(
        "mma.sync.aligned.m16n8k16.row.col.f32.f16.f16.f32 "
        "{%0,%1,%2,%3}, {%4,%5,%6,%7}, {%8,%9}, {%0,%1,%2,%3};"
        : "+f"(c[0]), "+f"(c[1]), "+f"(c[2]), "+f"(c[3])
        : "r"(a[0]), "r"(a[1]), "r"(a[2]), "r"(a[3]), "r"(b0), "r"(b1));
}
__device__ __forceinline__ void cp16(void* s, const void* g) {
    asm volatile("cp.async.cg.shared.global [%0], [%1], 16;"
                 :: "r"(smem_u32(s)), "l"(g));
}
#define CP_COMMIT() asm volatile("cp.async.commit_group;" ::)
#define CP_WAIT1()  asm volatile("cp.async.wait_group 1;" ::)

__device__ __forceinline__ void split2(float v, bf16& hi, bf16& lo) {
    hi = __float2bfloat16(v);
    lo = __float2bfloat16(v - __bfloat162float(hi));
}
__device__ __forceinline__ float sigmoidf_(float x) { return 1.0f / (1.0f + __expf(-x)); }
__device__ __forceinline__ float tanhf_(float x) {
    return 2.0f / (1.0f + __expf(-2.0f * x)) - 1.0f;
}

__device__ __forceinline__ void grid_sync() {
    __threadfence();
    __syncthreads();
    if (threadIdx.x == 0) {
        unsigned gen = *((volatile unsigned*)&g_bar_gen);
        if (atomicAdd(&g_bar_arrive, 1) == RN_NBLK - 1) {
            atomicExch(&g_bar_arrive, 0);
            __threadfence();
            atomicAdd(&g_bar_gen, 1);
        } else {
            while (*((volatile unsigned*)&g_bar_gen) == gen) __nanosleep(64);
        }
    }
    __syncthreads();
    __threadfence();
}

// ---------------- fused prep kernel (launch #1) -----------------------------
#define NC_BLKS 106496
#define NW_BLKS 6656
#define NH_BLKS 16384
#define NZ_BLKS 1024

__global__ __launch_bounds__(256) void prep_all(const float* __restrict__ xt,
                                                const float* __restrict__ xa,
                                                const float* __restrict__ xv,
                                                const float* __restrict__ W_ih,
                                                const float* __restrict__ W_hh) {
    int b = blockIdx.x;
    int tid = threadIdx.x;
    if (b < NC_BLKS) {
        size_t idx = (size_t)b * 256 + tid;
        int row = (int)(idx / D_PAD);
        int d   = (int)(idx % D_PAD);
        float v;
        if (d < 300)      v = xt[(size_t)row * 300 + d];
        else if (d < 374) v = xa[(size_t)row * 74 + (d - 300)];
        else if (d < 409) v = xv[(size_t)row * 35 + (d - 374)];
        else              v = 0.0f;
        bf16 hi, lo; split2(v, hi, lo);
        g_xcat_hi[idx] = hi; g_xcat_lo[idx] = lo;
    } else if (b < NC_BLKS + NW_BLKS) {
        int idx = (b - NC_BLKS) * 256 + tid;
        int r = idx / D_PAD, k = idx % D_PAD;
        int g_old = (r & 3) * H_SZ + (r >> 2);
        float v = (k < D_RAW) ? W_ih[(size_t)g_old * D_RAW + k] : 0.0f;
        bf16 hi, lo; split2(v, hi, lo);
        g_Wih_hi[idx] = hi; g_Wih_lo[idx] = lo;
    } else if (b < NC_BLKS + NW_BLKS + NH_BLKS) {
        int idx = (b - NC_BLKS - NW_BLKS) * 256 + tid;
        int r = idx >> 10, k = idx & 1023;
        int g_old = (r & 3) * H_SZ + (r >> 2);
        float v = W_hh[(size_t)g_old * H_SZ + k];
        __half hh = __float2half(v);
        __half hl = __float2half((v - __half2float(hh)) * LO_SCALE);
        g_Whh_h[idx] = hh; g_Whh_l[idx] = hl;
    } else {
        int idx = (b - NC_BLKS - NW_BLKS - NH_BLKS) * 256 + tid;
        g_hf[0][idx] = __float2half(0.0f);
        g_hf[1][idx] = __float2half(0.0f);
        if (idx == 0) { g_bar_arrive = 0; g_bar_gen = 0; }
    }
}

__global__ void dummy_kernel() {
    if (threadIdx.x == 0) g_bar_arrive = 0;
}

// ---------------- input projection GEMM (bf16 x3, launch #2) ----------------
#define XG_STG 20480

__device__ __forceinline__ void xg_issue(bf16* base, int bm, int bn, int k0, int tid) {
    bf16* Ah = base;
    bf16* Al = base + 5120;
    bf16* Bh = base + 10240;
    bf16* Bl = base + 15360;
    int r = tid >> 2, ch = (tid & 3) * 8;
#pragma unroll
    for (int rr = 0; rr < 2; rr++) {
        int row = r + rr * 64;
        cp16(&Ah[row * XLD + ch], &g_xcat_hi[(size_t)(bm + row) * D_PAD + k0 + ch]);
        cp16(&Al[row * XLD + ch], &g_xcat_lo[(size_t)(bm + row) * D_PAD + k0 + ch]);
        cp16(&Bh[row * XLD + ch], &g_Wih_hi[(size_t)(bn + row) * D_PAD + k0 + ch]);
        cp16(&Bl[row * XLD + ch], &g_Wih_lo[(size_t)(bn + row) * D_PAD + k0 + ch]);
    }
}

extern __shared__ __align__(1024) char shm_base[];

__global__ __launch_bounds__(256) void gemm_xg_mma(const float* __restrict__ bih,
                                                   const float* __restrict__ bhh) {
    bf16* dsm = (bf16*)shm_base;
    const int bm = blockIdx.x * 128;
    const int bn = blockIdx.y * 128;
    const int tid = threadIdx.x;
    const int wid = tid >> 5, lane = tid & 31;
    const int wm = wid >> 1, wn = wid & 1;

    float c[2][8][4];
#pragma unroll
    for (int i = 0; i < 2; i++)
#pragma unroll
        for (int j = 0; j < 8; j++)
#pragma unroll
            for (int q = 0; q < 4; q++) c[i][j][q] = 0.0f;

    const int arow = lane & 15, akoff = (lane >> 4) * 8;
    const int l8 = lane & 7, sel = lane >> 3;
    const int bnoff = l8 + (sel >> 1) * 8;
    const int bksel = (sel & 1) * 8;

    xg_issue(dsm,          bm, bn, 0,  tid); CP_COMMIT();
    xg_issue(dsm + XG_STG, bm, bn, 32, tid); CP_COMMIT();

    for (int kt = 0; kt < 13; kt++) {
        CP_WAIT1();
        __syncthreads();
        if (kt + 2 < 13) xg_issue(dsm + ((kt + 2) % 3) * XG_STG, bm, bn, (kt + 2) * 32, tid);
        CP_COMMIT();

        bf16* sAh = dsm + (kt % 3) * XG_STG;
        bf16* sAl = sAh + 5120;
        bf16* sBh = sAh + 10240;
        bf16* sBl = sAh + 15360;
#pragma unroll
        for (int kk = 0; kk < 32; kk += 16) {
            uint32_t ah[2][4], al[2][4];
#pragma unroll
            for (int mf = 0; mf < 2; mf++) {
                int roff = (wm * 32 + mf * 16 + arow) * XLD + kk + akoff;
                ldsm4(ah[mf][0], ah[mf][1], ah[mf][2], ah[mf][3], smem_u32(&sAh[roff]));
                ldsm4(al[mf][0], al[mf][1], al[mf][2], al[mf][3], smem_u32(&sAl[roff]));
            }
            uint32_t bh[8][2], bl[8][2];
#pragma unroll
            for (int p = 0; p < 4; p++) {
                int roff = (wn * 64 + p * 16 + bnoff) * XLD + kk + bksel;
                ldsm4(bh[2*p][0], bh[2*p][1], bh[2*p+1][0], bh[2*p+1][1], smem_u32(&sBh[roff]));
                ldsm4(bl[2*p][0], bl[2*p][1], bl[2*p+1][0], bl[2*p+1][1], smem_u32(&sBl[roff]));
            }
#pragma unroll
            for (int mf = 0; mf < 2; mf++)
#pragma unroll
                for (int nf = 0; nf < 8; nf++) {
                    mma16816_bf(c[mf][nf], ah[mf], bh[nf][0], bh[nf][1]);
                    mma16816_bf(c[mf][nf], ah[mf], bl[nf][0], bl[nf][1]);
                    mma16816_bf(c[mf][nf], al[mf], bh[nf][0], bh[nf][1]);
                }
        }
        __syncthreads();
    }

    const int grp = lane >> 2, tig = lane & 3;
#pragma unroll
    for (int mf = 0; mf < 2; mf++) {
#pragma unroll
        for (int nf = 0; nf < 8; nf++) {
            int m0 = bm + wm * 32 + mf * 16 + grp;
            int col = bn + wn * 64 + nf * 8 + 2 * tig;
            int o0 = (col & 3) * H_SZ + (col >> 2);
            int o1 = ((col + 1) & 3) * H_SZ + ((col + 1) >> 2);
            float bia0 = bih[o0] + bhh[o0];
            float bia1 = bih[o1] + bhh[o1];
#pragma unroll
            for (int rr = 0; rr < 2; rr++) {
                int m = m0 + rr * 8;
                int bb = m >> 8, tt = m & 255;
                float2 o;
                o.x = c[mf][nf][rr * 2 + 0] + bia0;
                o.y = c[mf][nf][rr * 2 + 1] + bia1;
                *(float2*)&g_xg[((size_t)tt * B_SZ + bb) * G4 + col] = o;
            }
        }
    }
}

// ---------------- persistent recurrence, W resident in SMEM (launch #4) -----
// grid 128, 1 CTA/SM. Each CTA: 32-gate slice, W hi+lo resident (160 KB smem),
// h streamed full-batch (M=256) in 32 chunks of K=32 via 3-stage cp.async.
// gates = h16*Wh + (h16*Wl')*2^-11 + xg  (2-term, proven 6.7e-5)
// SMEM halves layout:
//   [0, 40960)            Wh: 32 chunks x (32 rows x XLD 40)
//   [40960, 81920)        Wl
//   [81920, +3*10240)     A ring: stage = 256 rows x XLD 40
#define W_CHUNK_H 1280        // 32*40 halves per chunk
#define OFF_WL_H  40960
#define OFF_A_H   81920
#define A_STG_H   10240       // 256*40 halves
#define RN_SMEM   225280      // bytes = (81920 + 3*10240)*2

__device__ __forceinline__ void rn_issueA(__half* sm, int s, const __half* hf_r,
                                          int k0, int tid) {
    __half* A = sm + OFF_A_H + s * A_STG_H;
#pragma unroll
    for (int it = 0; it < 4; it++) {
        int idx = tid + it * 256;       // 1024 uint4 slots
        int row = idx >> 2, cg = idx & 3;
        cp16(&A[row * XLD + cg * 8], &hf_r[(size_t)row * H_SZ + k0 + cg * 8]);
    }
}

__global__ __launch_bounds__(256, 1) void lstm_resident2() {
    __half* sm = (__half*)shm_base;
    const int tid = threadIdx.x;
    const int wid = tid >> 5, lane = tid & 31;
    const int blk = blockIdx.x;           // 0..127
    const int bn = blk * 32;              // permuted gate slice
    const int wm = wid >> 1, wn = wid & 1;  // warp tile: M=64, N=16
    const int arow = lane & 15, akoff = (lane >> 4) * 8;
    const int l8 = lane & 7, sel = lane >> 3;
    const int bnoff = l8 + (sel >> 1) * 8;
    const int bksel = (sel & 1) * 8;
    const int grp = lane >> 2, tig = lane & 3;

    // ---- load resident W slice once (hi then lo), XLD-padded per chunk ----
    for (int i = tid; i < 8192; i += 256) {      // 8192 uint4 = 128 KB useful
        int hsel = i >> 12;                      // 0=hi, 1=lo
        int r = i & 4095;
        int kt = r >> 7, rem = r & 127;
        int row = rem >> 2, cg = rem & 3;
        const __half* src = hsel ? g_Whh_l : g_Whh_h;
        uint4 v = *(const uint4*)&src[(size_t)(bn + row) * H_SZ + kt * 32 + cg * 8];
        *(uint4*)&sm[(hsel ? OFF_WL_H : 0) + kt * W_CHUNK_H + row * XLD + cg * 8] = v;
    }
    __syncthreads();

    float creg[16];
#pragma unroll
    for (int u = 0; u < 16; u++) creg[u] = 0.0f;

    for (int t = 0; t < T_SZ; t++) {
        const __half* hf_r = g_hf[t & 1];
        __half* hf_w = g_hf[(t + 1) & 1];

        float c[4][2][4];    // h*Wh
        float c2[4][2][4];   // h*Wl' (scaled)
#pragma unroll
        for (int i = 0; i < 4; i++)
#pragma unroll
            for (int j = 0; j < 2; j++)
#pragma unroll
                for (int q = 0; q < 4; q++) { c[i][j][q] = 0.0f; c2[i][j][q] = 0.0f; }

        rn_issueA(sm, 0, hf_r, 0, tid);  CP_COMMIT();
        rn_issueA(sm, 1, hf_r, 32, tid); CP_COMMIT();

        for (int kt = 0; kt < 32; kt++) {
            CP_WAIT1();
            __syncthreads();
            if (kt + 2 < 32) rn_issueA(sm, (kt + 2) % 3, hf_r, (kt + 2) * 32, tid);
            CP_COMMIT();

            __half* sA  = sm + OFF_A_H + (kt % 3) * A_STG_H;
            __half* sBh = sm + kt * W_CHUNK_H;
            __half* sBl = sm + OFF_WL_H + kt * W_CHUNK_H;
#pragma unroll
            for (int kk = 0; kk < 32; kk += 16) {
                uint32_t ah[4][4];
#pragma unroll
                for (int mf = 0; mf < 4; mf++) {
                    int roff = (wm * 64 + mf * 16 + arow) * XLD + kk + akoff;
                    ldsm4(ah[mf][0], ah[mf][1], ah[mf][2], ah[mf][3], smem_u32(&sA[roff]));
                }
                uint32_t bh[2][2], bl[2][2];
                {
                    int roff = (wn * 16 + bnoff) * XLD + kk + bksel;
                    ldsm4(bh[0][0], bh[0][1], bh[1][0], bh[1][1], smem_u32(&sBh[roff]));
                    ldsm4(bl[0][0], bl[0][1], bl[1][0], bl[1][1], smem_u32(&sBl[roff]));
                }
#pragma unroll
                for (int mf = 0; mf < 4; mf++)
#pragma unroll
                    for (int nf = 0; nf < 2; nf++) {
                        mma16816_f16(c[mf][nf],  ah[mf], bh[nf][0], bh[nf][1]);
                        mma16816_f16(c2[mf][nf], ah[mf], bl[nf][0], bl[nf][1]);
                    }
            }
            __syncthreads();
        }

        // ---- fused LSTM pointwise epilogue ----
        const float* xgt = g_xg + (size_t)t * B_SZ * G4;
#pragma unroll
        for (int mf = 0; mf < 4; mf++) {
#pragma unroll
            for (int nf = 0; nf < 2; nf++) {
                int r0 = wm * 64 + mf * 16 + grp;     // batch row (bm = 0)
                int r1 = r0 + 8;
                int col = bn + wn * 16 + nf * 8 + 2 * tig;
                float2 x0 = *(const float2*)&xgt[(size_t)r0 * G4 + col];
                float2 x1 = *(const float2*)&xgt[(size_t)r1 * G4 + col];
                float g0 = c[mf][nf][0] + c2[mf][nf][0] * LO_INV + x0.x;
                float g1 = c[mf][nf][1] + c2[mf][nf][1] * LO_INV + x0.y;
                float g2 = c[mf][nf][2] + c2[mf][nf][2] * LO_INV + x1.x;
                float g3 = c[mf][nf][3] + c2[mf][nf][3] * LO_INV + x1.y;
                float p0 = __shfl_xor_sync(0xFFFFFFFFu, g0, 1);
                float p1 = __shfl_xor_sync(0xFFFFFFFFu, g1, 1);
                float p2 = __shfl_xor_sync(0xFFFFFFFFu, g2, 1);
                float p3 = __shfl_xor_sync(0xFFFFFFFFu, g3, 1);
                if ((tig & 1) == 0) {
                    int j = col >> 2;
                    int ui = (mf * 2 + nf) * 2;
                    {
                        float cn = sigmoidf_(g1) * creg[ui] + sigmoidf_(g0) * tanhf_(p0);
                        float hn = sigmoidf_(p1) * tanhf_(cn);
                        creg[ui] = cn;
                        size_t idx = (size_t)r0 * H_SZ + j;
                        hf_w[idx] = __float2half(hn);
                        if (t == T_SZ - 1) g_h[idx] = hn;
                    }
                    {
                        float cn = sigmoidf_(g3) * creg[ui + 1] + sigmoidf_(g2) * tanhf_(p2);
                        float hn = sigmoidf_(p3) * tanhf_(cn);
                        creg[ui + 1] = cn;
                        size_t idx = (size_t)r1 * H_SZ + j;
                        hf_w[idx] = __float2half(hn);
                        if (t == T_SZ - 1) g_h[idx] = hn;
                    }
                }
            }
        }
        grid_sync();
    }
}

// ---------------- MLP head --------------------------------------------------
__global__ __launch_bounds__(256) void mlp1_kernel(const float* __restrict__ W1,
                                                   const float* __restrict__ b1) {
    __shared__ float As[16][68];
    __shared__ float Bs[16][68];
    const int bm = blockIdx.x * 64;
    const int bn = blockIdx.y * 64;
    const int tid = threadIdx.x;
    const int tx = tid & 15, ty = tid >> 4;
    const int m0 = ty * 4, n0 = tx * 4;

    float acc[4][4];
#pragma unroll
    for (int i = 0; i < 4; i++)
#pragma unroll
        for (int j = 0; j < 4; j++) acc[i][j] = 0.0f;

    for (int k0 = 0; k0 < H_SZ; k0 += 16) {
        int row = tid >> 2;
        int kc = (tid & 3) * 4;
        float4 va = *(const float4*)&g_h[(size_t)(bm + row) * H_SZ + k0 + kc];
        As[kc + 0][row] = va.x; As[kc + 1][row] = va.y;
        As[kc + 2][row] = va.z; As[kc + 3][row] = va.w;
        float4 vb = *(const float4*)&W1[(size_t)(bn + row) * H_SZ + k0 + kc];
        Bs[kc + 0][row] = vb.x; Bs[kc + 1][row] = vb.y;
        Bs[kc + 2][row] = vb.z; Bs[kc + 3][row] = vb.w;
        __syncthreads();
#pragma unroll
        for (int k = 0; k < 16; k++) {
            float a[4], b[4];
            *(float4*)&a[0] = *(const float4*)&As[k][m0];
            *(float4*)&b[0] = *(const float4*)&Bs[k][n0];
#pragma unroll
            for (int i = 0; i < 4; i++)
#pragma unroll
                for (int j = 0; j < 4; j++) acc[i][j] = fmaf(a[i], b[j], acc[i][j]);
        }
        __syncthreads();
    }
#pragma unroll
    for (int i = 0; i < 4; i++) {
        int m = bm + m0 + i;
#pragma unroll
        for (int j = 0; j < 4; j++) {
            int n = bn + n0 + j;
            float v = acc[i][j] + b1[n];
            g_hidden[(size_t)m * CELL_SZ + n] = v > 0.0f ? v : 0.0f;
        }
    }
}

__global__ __launch_bounds__(128) void mlp2_kernel(const float* __restrict__ W2,
                                                   const float* __restrict__ b2,
                                                   float* __restrict__ out) {
    int b = blockIdx.x;
    int tid = threadIdx.x;
    float s = 0.0f;
    for (int j = tid; j < CELL_SZ; j += 128)
        s += g_hidden[(size_t)b * CELL_SZ + j] * W2[j];
#pragma unroll
    for (int off = 16; off > 0; off >>= 1)
        s += __shfl_down_sync(0xFFFFFFFFu, s, off);
    __shared__ float red[4];
    if ((tid & 31) == 0) red[tid >> 5] = s;
    __syncthreads();
    if (tid == 0) out[b] = red[0] + red[1] + red[2] + red[3] + b2[0];
}

// ---------------- launch ----------------------------------------------------
extern "C" void kernel_launch(void* const* d_in, const int* in_sizes, int n_in,
                              void* d_out, int out_size) {
    const float* x_text   = (const float*)d_in[0];
    const float* x_audio  = (const float*)d_in[1];
    const float* x_vision = (const float*)d_in[2];
    const float* W_ih = (const float*)d_in[3];
    const float* W_hh = (const float*)d_in[4];
    const float* b_ih = (const float*)d_in[5];
    const float* b_hh = (const float*)d_in[6];
    const float* W1 = (const float*)d_in[7];
    const float* b1 = (const float*)d_in[8];
    const float* W2 = (const float*)d_in[9];
    const float* b2 = (const float*)d_in[10];
    float* out = (float*)d_out;

    cudaFuncSetAttribute(gemm_xg_mma, cudaFuncAttributeMaxDynamicSharedMemorySize,
                         3 * XG_STG * (int)sizeof(bf16));
    cudaFuncSetAttribute(lstm_resident2, cudaFuncAttributeMaxDynamicSharedMemorySize,
                         RN_SMEM);

    // launch order chosen so the ncu-profiled slot (4th launch) = recurrence
    prep_all<<<NC_BLKS + NW_BLKS + NH_BLKS + NZ_BLKS, 256>>>(x_text, x_audio, x_vision,
                                                             W_ih, W_hh);
    gemm_xg_mma<<<dim3(512, 32), 256, 3 * XG_STG * sizeof(bf16)>>>(b_ih, b_hh);
    dummy_kernel<<<1, 32>>>();
    lstm_resident2<<<RN_NBLK, 256, RN_SMEM>>>();
    mlp1_kernel<<<dim3(4, 8), 256>>>(W1, b1);
    mlp2_kernel<<<256, 128>>>(W2, b2, out);
}

// round 14
// speedup vs baseline: 2.3311x; 2.3311x over previous
#include <cuda_runtime.h>
#include <cuda_bf16.h>
#include <cuda_fp16.h>
#include <math.h>
#include <stdint.h>

#define B_SZ 256
#define T_SZ 256
#define D_RAW 409
#define D_PAD 416
#define H_SZ 1024
#define G4 4096
#define CELL_SZ 512
#define MROWS (B_SZ * T_SZ)
#define XLD 40
#define RN_NBLK 128          // persistent recurrence grid (1 CTA/SM)
#define LO_SCALE 2048.0f
#define LO_INV   (1.0f / 2048.0f)

typedef __nv_bfloat16 bf16;

// ---------------- static device scratch ------------------------------------
__device__ bf16   g_xcat_hi[(size_t)MROWS * D_PAD];
__device__ bf16   g_xcat_lo[(size_t)MROWS * D_PAD];
__device__ bf16   g_Wih_hi[G4 * D_PAD];
__device__ bf16   g_Wih_lo[G4 * D_PAD];
__device__ __half g_Whh_h[G4 * H_SZ];       // rows permuted: r = 4*j + gate
__device__ __half g_Whh_l[G4 * H_SZ];       // (W - hi) * 2048
__device__ float  g_xg[(size_t)T_SZ * B_SZ * G4];   // [t][b][n_perm]
__device__ __half g_hf[2][B_SZ * H_SZ];     // h (fp16), double-buffered
__device__ float  g_h[B_SZ * H_SZ];         // fp32 h at t=255 (for MLP)
__device__ float  g_hidden[B_SZ * CELL_SZ];
__device__ unsigned g_bar_arrive;
__device__ unsigned g_bar_gen;

// ---------------- helpers --------------------------------------------------
__device__ __forceinline__ uint32_t smem_u32(const void* p) {
    return (uint32_t)__cvta_generic_to_shared(p);
}
__device__ __forceinline__ void ldsm4(uint32_t& r0, uint32_t& r1, uint32_t& r2,
                                      uint32_t& r3, uint32_t a) {
    asm volatile("ldmatrix.sync.aligned.m8n8.x4.shared.b16 {%0,%1,%2,%3}, [%4];"
                 : "=r"(r0), "=r"(r1), "=r"(r2), "=r"(r3) : "r"(a));
}
__device__ __forceinline__ void mma16816_bf(float c[4], const uint32_t a[4],
                                            uint32_t b0, uint32_t b1) {
    asm volatile(
        "mma.sync.aligned.m16n8k16.row.col.f32.bf16.bf16.f32 "
        "{%0,%1,%2,%3}, {%4,%5,%6,%7}, {%8,%9}, {%0,%1,%2,%3};"
        : "+f"(c[0]), "+f"(c[1]), "+f"(c[2]), "+f"(c[3])
        : "r"(a[0]), "r"(a[1]), "r"(a[2]), "r"(a[3]), "r"(b0), "r"(b1));
}
__device__ __forceinline__ void mma16816_f16(float c[4], const uint32_t a[4],
                                             uint32_t b0, uint32_t b1) {
    asm volatile(
        "mma.sync.aligned.m16n8k16.row.col.f32.f16.f16.f32 "
        "{%0,%1,%2,%3}, {%4,%5,%6,%7}, {%8,%9}, {%0,%1,%2,%3};"
        : "+f"(c[0]), "+f"(c[1]), "+f"(c[2]), "+f"(c[3])
        : "r"(a[0]), "r"(a[1]), "r"(a[2]), "r"(a[3]), "r"(b0), "r"(b1));
}
__device__ __forceinline__ void cp16(void* s, const void* g) {
    asm volatile("cp.async.cg.shared.global [%0], [%1], 16;"
                 :: "r"(smem_u32(s)), "l"(g));
}
#define CP_COMMIT() asm volatile("cp.async.commit_group;" ::)
#define CP_WAIT1()  asm volatile("cp.async.wait_group 1;" ::)

__device__ __forceinline__ void split2(float v, bf16& hi, bf16& lo) {
    hi = __float2bfloat16(v);
    lo = __float2bfloat16(v - __bfloat162float(hi));
}
__device__ __forceinline__ float sigmoidf_(float x) { return 1.0f / (1.0f + __expf(-x)); }
__device__ __forceinline__ float tanhf_(float x) {
    return 2.0f / (1.0f + __expf(-2.0f * x)) - 1.0f;
}

__device__ __forceinline__ void grid_sync() {
    __threadfence();
    __syncthreads();
    if (threadIdx.x == 0) {
        unsigned gen = *((volatile unsigned*)&g_bar_gen);
        if (atomicAdd(&g_bar_arrive, 1) == RN_NBLK - 1) {
            atomicExch(&g_bar_arrive, 0);
            __threadfence();
            atomicAdd(&g_bar_gen, 1);
        } else {
            while (*((volatile unsigned*)&g_bar_gen) == gen) __nanosleep(64);
        }
    }
    __syncthreads();
    __threadfence();
}

// ---------------- fused prep kernel (launch #1) -----------------------------
#define NC_BLKS 106496
#define NW_BLKS 6656
#define NH_BLKS 16384
#define NZ_BLKS 1024

__global__ __launch_bounds__(256) void prep_all(const float* __restrict__ xt,
                                                const float* __restrict__ xa,
                                                const float* __restrict__ xv,
                                                const float* __restrict__ W_ih,
                                                const float* __restrict__ W_hh) {
    int b = blockIdx.x;
    int tid = threadIdx.x;
    if (b < NC_BLKS) {
        size_t idx = (size_t)b * 256 + tid;
        int row = (int)(idx / D_PAD);
        int d   = (int)(idx % D_PAD);
        float v;
        if (d < 300)      v = xt[(size_t)row * 300 + d];
        else if (d < 374) v = xa[(size_t)row * 74 + (d - 300)];
        else if (d < 409) v = xv[(size_t)row * 35 + (d - 374)];
        else              v = 0.0f;
        bf16 hi, lo; split2(v, hi, lo);
        g_xcat_hi[idx] = hi; g_xcat_lo[idx] = lo;
    } else if (b < NC_BLKS + NW_BLKS) {
        int idx = (b - NC_BLKS) * 256 + tid;
        int r = idx / D_PAD, k = idx % D_PAD;
        int g_old = (r & 3) * H_SZ + (r >> 2);
        float v = (k < D_RAW) ? W_ih[(size_t)g_old * D_RAW + k] : 0.0f;
        bf16 hi, lo; split2(v, hi, lo);
        g_Wih_hi[idx] = hi; g_Wih_lo[idx] = lo;
    } else if (b < NC_BLKS + NW_BLKS + NH_BLKS) {
        int idx = (b - NC_BLKS - NW_BLKS) * 256 + tid;
        int r = idx >> 10, k = idx & 1023;
        int g_old = (r & 3) * H_SZ + (r >> 2);
        float v = W_hh[(size_t)g_old * H_SZ + k];
        __half hh = __float2half(v);
        __half hl = __float2half((v - __half2float(hh)) * LO_SCALE);
        g_Whh_h[idx] = hh; g_Whh_l[idx] = hl;
    } else {
        int idx = (b - NC_BLKS - NW_BLKS - NH_BLKS) * 256 + tid;
        g_hf[0][idx] = __float2half(0.0f);
        g_hf[1][idx] = __float2half(0.0f);
        if (idx == 0) { g_bar_arrive = 0; g_bar_gen = 0; }
    }
}

__global__ void dummy_kernel() {
    if (threadIdx.x == 0) g_bar_arrive = 0;
}

// ---------------- input projection GEMM (bf16 x3, launch #2) ----------------
#define XG_STG 20480

__device__ __forceinline__ void xg_issue(bf16* base, int bm, int bn, int k0, int tid) {
    bf16* Ah = base;
    bf16* Al = base + 5120;
    bf16* Bh = base + 10240;
    bf16* Bl = base + 15360;
    int r = tid >> 2, ch = (tid & 3) * 8;
#pragma unroll
    for (int rr = 0; rr < 2; rr++) {
        int row = r + rr * 64;
        cp16(&Ah[row * XLD + ch], &g_xcat_hi[(size_t)(bm + row) * D_PAD + k0 + ch]);
        cp16(&Al[row * XLD + ch], &g_xcat_lo[(size_t)(bm + row) * D_PAD + k0 + ch]);
        cp16(&Bh[row * XLD + ch], &g_Wih_hi[(size_t)(bn + row) * D_PAD + k0 + ch]);
        cp16(&Bl[row * XLD + ch], &g_Wih_lo[(size_t)(bn + row) * D_PAD + k0 + ch]);
    }
}

extern __shared__ __align__(1024) char shm_base[];

__global__ __launch_bounds__(256) void gemm_xg_mma(const float* __restrict__ bih,
                                                   const float* __restrict__ bhh) {
    bf16* dsm = (bf16*)shm_base;
    const int bm = blockIdx.x * 128;
    const int bn = blockIdx.y * 128;
    const int tid = threadIdx.x;
    const int wid = tid >> 5, lane = tid & 31;
    const int wm = wid >> 1, wn = wid & 1;

    float c[2][8][4];
#pragma unroll
    for (int i = 0; i < 2; i++)
#pragma unroll
        for (int j = 0; j < 8; j++)
#pragma unroll
            for (int q = 0; q < 4; q++) c[i][j][q] = 0.0f;

    const int arow = lane & 15, akoff = (lane >> 4) * 8;
    const int l8 = lane & 7, sel = lane >> 3;
    const int bnoff = l8 + (sel >> 1) * 8;
    const int bksel = (sel & 1) * 8;

    xg_issue(dsm,          bm, bn, 0,  tid); CP_COMMIT();
    xg_issue(dsm + XG_STG, bm, bn, 32, tid); CP_COMMIT();

    for (int kt = 0; kt < 13; kt++) {
        CP_WAIT1();
        __syncthreads();
        if (kt + 2 < 13) xg_issue(dsm + ((kt + 2) % 3) * XG_STG, bm, bn, (kt + 2) * 32, tid);
        CP_COMMIT();

        bf16* sAh = dsm + (kt % 3) * XG_STG;
        bf16* sAl = sAh + 5120;
        bf16* sBh = sAh + 10240;
        bf16* sBl = sAh + 15360;
#pragma unroll
        for (int kk = 0; kk < 32; kk += 16) {
            uint32_t ah[2][4], al[2][4];
#pragma unroll
            for (int mf = 0; mf < 2; mf++) {
                int roff = (wm * 32 + mf * 16 + arow) * XLD + kk + akoff;
                ldsm4(ah[mf][0], ah[mf][1], ah[mf][2], ah[mf][3], smem_u32(&sAh[roff]));
                ldsm4(al[mf][0], al[mf][1], al[mf][2], al[mf][3], smem_u32(&sAl[roff]));
            }
            uint32_t bh[8][2], bl[8][2];
#pragma unroll
            for (int p = 0; p < 4; p++) {
                int roff = (wn * 64 + p * 16 + bnoff) * XLD + kk + bksel;
                ldsm4(bh[2*p][0], bh[2*p][1], bh[2*p+1][0], bh[2*p+1][1], smem_u32(&sBh[roff]));
                ldsm4(bl[2*p][0], bl[2*p][1], bl[2*p+1][0], bl[2*p+1][1], smem_u32(&sBl[roff]));
            }
#pragma unroll
            for (int mf = 0; mf < 2; mf++)
#pragma unroll
                for (int nf = 0; nf < 8; nf++) {
                    mma16816_bf(c[mf][nf], ah[mf], bh[nf][0], bh[nf][1]);
                    mma16816_bf(c[mf][nf], ah[mf], bl[nf][0], bl[nf][1]);
                    mma16816_bf(c[mf][nf], al[mf], bh[nf][0], bh[nf][1]);
                }
        }
        __syncthreads();
    }

    const int grp = lane >> 2, tig = lane & 3;
#pragma unroll
    for (int mf = 0; mf < 2; mf++) {
#pragma unroll
        for (int nf = 0; nf < 8; nf++) {
            int m0 = bm + wm * 32 + mf * 16 + grp;
            int col = bn + wn * 64 + nf * 8 + 2 * tig;
            int o0 = (col & 3) * H_SZ + (col >> 2);
            int o1 = ((col + 1) & 3) * H_SZ + ((col + 1) >> 2);
            float bia0 = bih[o0] + bhh[o0];
            float bia1 = bih[o1] + bhh[o1];
#pragma unroll
            for (int rr = 0; rr < 2; rr++) {
                int m = m0 + rr * 8;
                int bb = m >> 8, tt = m & 255;
                float2 o;
                o.x = c[mf][nf][rr * 2 + 0] + bia0;
                o.y = c[mf][nf][rr * 2 + 1] + bia1;
                *(float2*)&g_xg[((size_t)tt * B_SZ + bb) * G4 + col] = o;
            }
        }
    }
}

// ---------------- persistent warp-autonomous recurrence (launch #4) ---------
// grid 128 (1 CTA/SM), 512 threads (16 warps). CTA owns gate slice N=32 with
// W hi+lo RESIDENT in smem. Warp w owns batch rows [16w, 16w+16): streams its
// own A through a private 3-stage cp.async ring — NO __syncthreads in k-loop.
// FIX vs R13: TWO cp16 per lane per chunk (full 16x32 coverage; R13 loaded
// only half of each A tile -> garbage).
// gates = h16*Wh + (h16*Wl')*2^-11 + xg  (2-term, proven 6.7e-5)
#define RW_WL    40960
#define RW_A     81920
#define A_WSTR   1920        // halves per warp (3 stages x 640)
#define A_SSTR   640         // halves per stage
#define RN_SMEM  225280      // bytes = (81920 + 16*1920) * 2

__global__ __launch_bounds__(512, 1) void lstm_wres() {
    __half* sm = (__half*)shm_base;
    const int tid = threadIdx.x;
    const int wid = tid >> 5, lane = tid & 31;
    const int blk = blockIdx.x;           // 0..127
    const int bn = blk * 32;              // permuted gate slice
    const int arow = lane & 15, akoff = (lane >> 4) * 8;
    const int l8 = lane & 7, sel = lane >> 3;
    const int bnoff = l8 + (sel >> 1) * 8;
    const int bksel = (sel & 1) * 8;
    const int grp = lane >> 2, tig = lane & 3;

    // ---- load resident W (hi+lo), one time: 8192 uint4, 16 per thread ----
    for (int i = tid; i < 8192; i += 512) {
        int hsel = i >> 12;
        int r = i & 4095;
        int kt = r >> 7, rem = r & 127;
        int row = rem >> 2, cg = rem & 3;
        const __half* src = hsel ? g_Whh_l : g_Whh_h;
        uint4 v = *(const uint4*)&src[(size_t)(bn + row) * H_SZ + kt * 32 + cg * 8];
        *(uint4*)&sm[(hsel ? RW_WL : 0) + kt * 1280 + row * 40 + cg * 8] = v;
    }
    __syncthreads();

    __half* Aw = sm + RW_A + wid * A_WSTR;
    const int a_r = lane >> 1;              // 0..15 (row)
    const int a_c = (lane & 1) * 16;        // halves 0 or 16; each lane does 2 cp16

    float creg[8];
#pragma unroll
    for (int u = 0; u < 8; u++) creg[u] = 0.0f;

    for (int t = 0; t < T_SZ; t++) {
        const __half* hf_r = g_hf[t & 1];
        __half* hf_w = g_hf[(t + 1) & 1];
        const __half* hrow = hf_r + (size_t)(wid * 16) * H_SZ;

        float c[4][4], c2[4][4];
#pragma unroll
        for (int j = 0; j < 4; j++)
#pragma unroll
            for (int q = 0; q < 4; q++) { c[j][q] = 0.0f; c2[j][q] = 0.0f; }

        // per-warp prologue: stages 0,1 (full coverage: 2 cp16/lane)
#pragma unroll
        for (int p = 0; p < 2; p++) {
            int k0 = p * 32;
            cp16(&Aw[p * A_SSTR + a_r * XLD + a_c],
                 &hrow[(size_t)a_r * H_SZ + k0 + a_c]);
            cp16(&Aw[p * A_SSTR + a_r * XLD + a_c + 8],
                 &hrow[(size_t)a_r * H_SZ + k0 + a_c + 8]);
            CP_COMMIT();
        }

        for (int kt = 0; kt < 32; kt++) {
            CP_WAIT1();
            __syncwarp();
            if (kt + 2 < 32) {
                int s = kt + 2 - ((kt + 2) / 3) * 3;
                int k0 = (kt + 2) * 32;
                cp16(&Aw[s * A_SSTR + a_r * XLD + a_c],
                     &hrow[(size_t)a_r * H_SZ + k0 + a_c]);
                cp16(&Aw[s * A_SSTR + a_r * XLD + a_c + 8],
                     &hrow[(size_t)a_r * H_SZ + k0 + a_c + 8]);
            }
            CP_COMMIT();

            __half* sA  = Aw + (kt - (kt / 3) * 3) * A_SSTR;
            __half* sBh = sm + kt * 1280;
            __half* sBl = sm + RW_WL + kt * 1280;
#pragma unroll
            for (int kk = 0; kk < 32; kk += 16) {
                uint32_t a[4];
                ldsm4(a[0], a[1], a[2], a[3], smem_u32(&sA[arow * XLD + kk + akoff]));
                uint32_t bh[4][2], bl[4][2];
#pragma unroll
                for (int p = 0; p < 2; p++) {
                    int roff = (p * 16 + bnoff) * XLD + kk + bksel;
                    ldsm4(bh[2*p][0], bh[2*p][1], bh[2*p+1][0], bh[2*p+1][1],
                          smem_u32(&sBh[roff]));
                    ldsm4(bl[2*p][0], bl[2*p][1], bl[2*p+1][0], bl[2*p+1][1],
                          smem_u32(&sBl[roff]));
                }
#pragma unroll
                for (int nf = 0; nf < 4; nf++) {
                    mma16816_f16(c[nf],  a, bh[nf][0], bh[nf][1]);
                    mma16816_f16(c2[nf], a, bl[nf][0], bl[nf][1]);
                }
            }
        }

        // ---- fused LSTM pointwise epilogue (per warp, rows 16w..16w+16) ----
        const float* xgt = g_xg + (size_t)t * B_SZ * G4;
#pragma unroll
        for (int nf = 0; nf < 4; nf++) {
            int r0 = wid * 16 + grp;
            int r1 = r0 + 8;
            int col = bn + nf * 8 + 2 * tig;
            float2 x0 = *(const float2*)&xgt[(size_t)r0 * G4 + col];
            float2 x1 = *(const float2*)&xgt[(size_t)r1 * G4 + col];
            float g0 = c[nf][0] + c2[nf][0] * LO_INV + x0.x;
            float g1 = c[nf][1] + c2[nf][1] * LO_INV + x0.y;
            float g2 = c[nf][2] + c2[nf][2] * LO_INV + x1.x;
            float g3 = c[nf][3] + c2[nf][3] * LO_INV + x1.y;
            float p0 = __shfl_xor_sync(0xFFFFFFFFu, g0, 1);
            float p1 = __shfl_xor_sync(0xFFFFFFFFu, g1, 1);
            float p2 = __shfl_xor_sync(0xFFFFFFFFu, g2, 1);
            float p3 = __shfl_xor_sync(0xFFFFFFFFu, g3, 1);
            if ((tig & 1) == 0) {
                int j = col >> 2;
                int ui = nf * 2;
                {
                    float cn = sigmoidf_(g1) * creg[ui] + sigmoidf_(g0) * tanhf_(p0);
                    float hn = sigmoidf_(p1) * tanhf_(cn);
                    creg[ui] = cn;
                    size_t idx = (size_t)r0 * H_SZ + j;
                    hf_w[idx] = __float2half(hn);
                    if (t == T_SZ - 1) g_h[idx] = hn;
                }
                {
                    float cn = sigmoidf_(g3) * creg[ui + 1] + sigmoidf_(g2) * tanhf_(p2);
                    float hn = sigmoidf_(p3) * tanhf_(cn);
                    creg[ui + 1] = cn;
                    size_t idx = (size_t)r1 * H_SZ + j;
                    hf_w[idx] = __float2half(hn);
                    if (t == T_SZ - 1) g_h[idx] = hn;
                }
            }
        }
        grid_sync();
    }
}

// ---------------- MLP head --------------------------------------------------
__global__ __launch_bounds__(256) void mlp1_kernel(const float* __restrict__ W1,
                                                   const float* __restrict__ b1) {
    __shared__ float As[16][68];
    __shared__ float Bs[16][68];
    const int bm = blockIdx.x * 64;
    const int bn = blockIdx.y * 64;
    const int tid = threadIdx.x;
    const int tx = tid & 15, ty = tid >> 4;
    const int m0 = ty * 4, n0 = tx * 4;

    float acc[4][4];
#pragma unroll
    for (int i = 0; i < 4; i++)
#pragma unroll
        for (int j = 0; j < 4; j++) acc[i][j] = 0.0f;

    for (int k0 = 0; k0 < H_SZ; k0 += 16) {
        int row = tid >> 2;
        int kc = (tid & 3) * 4;
        float4 va = *(const float4*)&g_h[(size_t)(bm + row) * H_SZ + k0 + kc];
        As[kc + 0][row] = va.x; As[kc + 1][row] = va.y;
        As[kc + 2][row] = va.z; As[kc + 3][row] = va.w;
        float4 vb = *(const float4*)&W1[(size_t)(bn + row) * H_SZ + k0 + kc];
        Bs[kc + 0][row] = vb.x; Bs[kc + 1][row] = vb.y;
        Bs[kc + 2][row] = vb.z; Bs[kc + 3][row] = vb.w;
        __syncthreads();
#pragma unroll
        for (int k = 0; k < 16; k++) {
            float a[4], b[4];
            *(float4*)&a[0] = *(const float4*)&As[k][m0];
            *(float4*)&b[0] = *(const float4*)&Bs[k][n0];
#pragma unroll
            for (int i = 0; i < 4; i++)
#pragma unroll
                for (int j = 0; j < 4; j++) acc[i][j] = fmaf(a[i], b[j], acc[i][j]);
        }
        __syncthreads();
    }
#pragma unroll
    for (int i = 0; i < 4; i++) {
        int m = bm + m0 + i;
#pragma unroll
        for (int j = 0; j < 4; j++) {
            int n = bn + n0 + j;
            float v = acc[i][j] + b1[n];
            g_hidden[(size_t)m * CELL_SZ + n] = v > 0.0f ? v : 0.0f;
        }
    }
}

__global__ __launch_bounds__(128) void mlp2_kernel(const float* __restrict__ W2,
                                                   const float* __restrict__ b2,
                                                   float* __restrict__ out) {
    int b = blockIdx.x;
    int tid = threadIdx.x;
    float s = 0.0f;
    for (int j = tid; j < CELL_SZ; j += 128)
        s += g_hidden[(size_t)b * CELL_SZ + j] * W2[j];
#pragma unroll
    for (int off = 16; off > 0; off >>= 1)
        s += __shfl_down_sync(0xFFFFFFFFu, s, off);
    __shared__ float red[4];
    if ((tid & 31) == 0) red[tid >> 5] = s;
    __syncthreads();
    if (tid == 0) out[b] = red[0] + red[1] + red[2] + red[3] + b2[0];
}

// ---------------- launch ----------------------------------------------------
extern "C" void kernel_launch(void* const* d_in, const int* in_sizes, int n_in,
                              void* d_out, int out_size) {
    const float* x_text   = (const float*)d_in[0];
    const float* x_audio  = (const float*)d_in[1];
    const float* x_vision = (const float*)d_in[2];
    const float* W_ih = (const float*)d_in[3];
    const float* W_hh = (const float*)d_in[4];
    const float* b_ih = (const float*)d_in[5];
    const float* b_hh = (const float*)d_in[6];
    const float* W1 = (const float*)d_in[7];
    const float* b1 = (const float*)d_in[8];
    const float* W2 = (const float*)d_in[9];
    const float* b2 = (const float*)d_in[10];
    float* out = (float*)d_out;

    cudaFuncSetAttribute(gemm_xg_mma, cudaFuncAttributeMaxDynamicSharedMemorySize,
                         3 * XG_STG * (int)sizeof(bf16));
    cudaFuncSetAttribute(lstm_wres, cudaFuncAttributeMaxDynamicSharedMemorySize,
                         RN_SMEM);

    // launch order keeps the ncu-profiled slot (4th launch) = recurrence
    prep_all<<<NC_BLKS + NW_BLKS + NH_BLKS + NZ_BLKS, 256>>>(x_text, x_audio, x_vision,
                                                             W_ih, W_hh);
    gemm_xg_mma<<<dim3(512, 32), 256, 3 * XG_STG * sizeof(bf16)>>>(b_ih, b_hh);
    dummy_kernel<<<1, 32>>>();
    lstm_wres<<<RN_NBLK, 512, RN_SMEM>>>();
    mlp1_kernel<<<dim3(4, 8), 256>>>(W1, b1);
    mlp2_kernel<<<256, 128>>>(W2, b2, out);
}